// round 4
// baseline (speedup 1.0000x reference)
#include <cuda_runtime.h>
#include <cstdint>

// AlmostFairKCRPSLoss — persistent-CTA TMA(bulk)+mbarrier pipeline version.
// crps(s) = mean_i|p_i - t| - sum_{i<j}|p_i-p_j|/240  (m=16, ALPHA=1)
// spread via 16-input Batcher sort (63 CAS) + rank weights (2k-15).
//
// 296 persistent CTAs x 288 threads. Warp 0 lane 0 = TMA producer
// (cp.async.bulk 1D, 17 x 1KB per 256-location tile), warps 1-8 = 256
// compute threads reading staged smem. 4-stage ring, full/empty mbarriers.
// Single launch; last-CTA-done final reduction; ticket reset for graph replay.

static constexpr int M_ENS = 16;
static constexpr int NLOC = 6 * 2 * 192 * 288;   // 663552
static constexpr int TILE = 256;                  // locations per tile
static constexpr int NTILES = NLOC / TILE;        // 2592
static constexpr int CTAS = 296;                  // 2 per SM
static constexpr int THREADS = 288;               // 1 producer warp + 256 compute
static constexpr int STAGES = 4;
static constexpr int STREAMS = M_ENS + 1;         // 16 members + target
static constexpr uint32_t STAGE_BYTES = STREAMS * TILE * 4;  // 17408
static constexpr int STAGE_FLOATS = STREAMS * TILE;
static constexpr uint32_t DYN_SMEM = STAGES * STAGE_BYTES;   // 69632

__device__ float g_part[CTAS];
__device__ unsigned int g_ticket = 0;  // reset by last CTA each launch

// ---------- PTX helpers ----------
__device__ __forceinline__ uint32_t smem_u32(const void* p) {
    uint32_t a;
    asm("{ .reg .u64 t; cvta.to.shared.u64 t, %1; cvt.u32.u64 %0, t; }"
        : "=r"(a) : "l"(p));
    return a;
}
__device__ __forceinline__ void mbar_init(uint32_t a, uint32_t cnt) {
    asm volatile("mbarrier.init.shared.b64 [%0], %1;" :: "r"(a), "r"(cnt) : "memory");
}
__device__ __forceinline__ void mbar_expect_tx(uint32_t a, uint32_t bytes) {
    asm volatile("mbarrier.arrive.expect_tx.shared.b64 _, [%0], %1;"
                 :: "r"(a), "r"(bytes) : "memory");
}
__device__ __forceinline__ void mbar_arrive(uint32_t a) {
    asm volatile("mbarrier.arrive.shared.b64 _, [%0];" :: "r"(a) : "memory");
}
__device__ __forceinline__ void mbar_wait(uint32_t a, uint32_t parity) {
    uint32_t done;
    asm volatile(
        "{\n .reg .pred p;\n"
        " mbarrier.try_wait.parity.acquire.cta.shared::cta.b64 p, [%1], %2;\n"
        " selp.b32 %0, 1, 0, p;\n}"
        : "=r"(done) : "r"(a), "r"(parity) : "memory");
    while (!done) {
        asm volatile(
            "{\n .reg .pred p;\n"
            " mbarrier.try_wait.parity.acquire.cta.shared::cta.b64 p, [%1], %2, 0x989680;\n"
            " selp.b32 %0, 1, 0, p;\n}"
            : "=r"(done) : "r"(a), "r"(parity) : "memory");
    }
}
__device__ __forceinline__ void bulk_g2s(uint32_t dst, const void* src,
                                         uint32_t bytes, uint32_t mbar) {
    asm volatile(
        "cp.async.bulk.shared::cta.global.mbarrier::complete_tx::bytes "
        "[%0], [%1], %2, [%3];"
        :: "r"(dst), "l"(src), "r"(bytes), "r"(mbar) : "memory");
}

#define CAS(a, b)                          \
    do {                                   \
        float _lo = fminf(p[a], p[b]);     \
        float _hi = fmaxf(p[a], p[b]);     \
        p[a] = _lo;                        \
        p[b] = _hi;                        \
    } while (0)

__global__ __launch_bounds__(THREADS) void crps_kernel(
    const float* __restrict__ target, const float* __restrict__ pred,
    float* __restrict__ out) {
    extern __shared__ float dyn[];  // [STAGES][STREAMS][TILE]
    __shared__ __align__(8) unsigned long long s_full[STAGES], s_empty[STAGES];

    const int tid = threadIdx.x;
    const int bid = blockIdx.x;
    const uint32_t smem_base = smem_u32(dyn);

    if (tid == 0) {
#pragma unroll
        for (int s = 0; s < STAGES; s++) {
            mbar_init(smem_u32(&s_full[s]), 1);       // producer's expect_tx arrive
            mbar_init(smem_u32(&s_empty[s]), 256);    // all compute threads
        }
    }
    __syncthreads();

    float crps_acc = 0.0f;

    if (tid < 32) {
        // ---------- producer warp (only lane 0 works) ----------
        if (tid == 0) {
            int stage = 0, phase = 1;  // empty-wait passes immediately first lap
            for (int tile = bid; tile < NTILES; tile += CTAS) {
                const uint32_t eb = smem_u32(&s_empty[stage]);
                const uint32_t fb = smem_u32(&s_full[stage]);
                mbar_wait(eb, (uint32_t)phase);
                mbar_expect_tx(fb, STAGE_BYTES);
                const uint32_t dst0 = smem_base + stage * STAGE_BYTES;
                const long long base = (long long)tile * TILE;
#pragma unroll
                for (int i = 0; i < M_ENS; i++) {
                    bulk_g2s(dst0 + i * (TILE * 4),
                             pred + (long long)i * NLOC + base, TILE * 4, fb);
                }
                bulk_g2s(dst0 + M_ENS * (TILE * 4), target + base, TILE * 4, fb);
                if (++stage == STAGES) { stage = 0; phase ^= 1; }
            }
        }
    } else {
        // ---------- compute threads ----------
        const int loc = tid - 32;  // 0..255
        int stage = 0, phase = 0;
        for (int tile = bid; tile < NTILES; tile += CTAS) {
            const uint32_t fb = smem_u32(&s_full[stage]);
            const uint32_t eb = smem_u32(&s_empty[stage]);
            mbar_wait(fb, (uint32_t)phase);

            const float* buf = dyn + stage * STAGE_FLOATS;
            float p[M_ENS];
#pragma unroll
            for (int i = 0; i < M_ENS; i++) p[i] = buf[i * TILE + loc];
            const float t = buf[M_ENS * TILE + loc];

            float skill = 0.0f;
#pragma unroll
            for (int i = 0; i < M_ENS; i++) skill += fabsf(p[i] - t);

            // Batcher merge-exchange network, 16 inputs, 63 comparators
            CAS(0, 8);  CAS(1, 9);  CAS(2, 10); CAS(3, 11);
            CAS(4, 12); CAS(5, 13); CAS(6, 14); CAS(7, 15);
            CAS(0, 4);  CAS(1, 5);  CAS(2, 6);  CAS(3, 7);
            CAS(8, 12); CAS(9, 13); CAS(10, 14); CAS(11, 15);
            CAS(4, 8);  CAS(5, 9);  CAS(6, 10); CAS(7, 11);
            CAS(0, 2);  CAS(1, 3);  CAS(4, 6);  CAS(5, 7);
            CAS(8, 10); CAS(9, 11); CAS(12, 14); CAS(13, 15);
            CAS(2, 8);  CAS(3, 9);  CAS(6, 12); CAS(7, 13);
            CAS(2, 4);  CAS(3, 5);  CAS(6, 8);  CAS(7, 9);
            CAS(10, 12); CAS(11, 13);
            CAS(0, 1);  CAS(2, 3);  CAS(4, 5);  CAS(6, 7);
            CAS(8, 9);  CAS(10, 11); CAS(12, 13); CAS(14, 15);
            CAS(1, 8);  CAS(3, 10); CAS(5, 12); CAS(7, 14);
            CAS(1, 4);  CAS(3, 6);  CAS(5, 8);  CAS(7, 10);
            CAS(9, 12); CAS(11, 14);
            CAS(1, 2);  CAS(3, 4);  CAS(5, 6);  CAS(7, 8);
            CAS(9, 10); CAS(11, 12); CAS(13, 14);

            float ws = 0.0f;
#pragma unroll
            for (int k = 0; k < M_ENS; k++)
                ws = fmaf((float)(2 * k - 15), p[k], ws);

            crps_acc += skill * (1.0f / 16.0f) - ws * (1.0f / 240.0f);

            mbar_arrive(eb);
            if (++stage == STAGES) { stage = 0; phase ^= 1; }
        }
    }

    // ---------- block reduction over all 288 threads (producer warp adds 0) ----------
    __syncthreads();
    __shared__ float warp_sums[THREADS / 32];  // 9 warps
    float v = crps_acc;
#pragma unroll
    for (int o = 16; o > 0; o >>= 1) v += __shfl_xor_sync(0xFFFFFFFFu, v, o);
    const int lane = tid & 31;
    const int wid = tid >> 5;
    if (lane == 0) warp_sums[wid] = v;
    __syncthreads();

    __shared__ bool s_last;
    if (wid == 0) {
        float bv = (lane < (THREADS / 32)) ? warp_sums[lane] : 0.0f;
#pragma unroll
        for (int o = 8; o > 0; o >>= 1) bv += __shfl_xor_sync(0xFFFFFFFFu, bv, o);
        if (lane == 0) {
            g_part[bid] = bv;
            __threadfence();
            unsigned int tk = atomicAdd(&g_ticket, 1u);
            s_last = (tk == (unsigned int)(CTAS - 1));
        }
    }
    __syncthreads();

    if (s_last) {
        double acc = 0.0;
        for (int i = tid; i < CTAS; i += THREADS) acc += (double)g_part[i];
#pragma unroll
        for (int o = 16; o > 0; o >>= 1) acc += __shfl_xor_sync(0xFFFFFFFFu, acc, o);
        __shared__ double warp_d[THREADS / 32];
        if (lane == 0) warp_d[wid] = acc;
        __syncthreads();
        if (wid == 0) {
            double bd = (lane < (THREADS / 32)) ? warp_d[lane] : 0.0;
#pragma unroll
            for (int o = 8; o > 0; o >>= 1) bd += __shfl_xor_sync(0xFFFFFFFFu, bd, o);
            if (lane == 0) {
                out[0] = (float)(bd / (double)NLOC);
                __threadfence();
                g_ticket = 0;  // deterministic across graph replays
            }
        }
    }
}

extern "C" void kernel_launch(void* const* d_in, const int* in_sizes, int n_in,
                              void* d_out, int out_size) {
    const float* a = (const float*)d_in[0];
    const float* b = (const float*)d_in[1];
    const float* target = a;
    const float* pred = b;
    if (n_in >= 2 && in_sizes[0] > in_sizes[1]) {
        target = b;
        pred = a;
    }
    cudaFuncSetAttribute(crps_kernel, cudaFuncAttributeMaxDynamicSharedMemorySize,
                         DYN_SMEM);
    crps_kernel<<<CTAS, THREADS, DYN_SMEM>>>(target, pred, (float*)d_out);
}

// round 5
// speedup vs baseline: 1.2265x; 1.2265x over previous
#include <cuda_runtime.h>
#include <cuda_fp16.h>
#include <cstdint>

// AlmostFairKCRPSLoss — single launch, half2-packed compute (2 locations/thread).
// crps(s) = mean_i|p_i - t| - sum_{i<j}|p_i-p_j|/240  (m=16, ALPHA=1)
// spread via 16-input Batcher sort in __half2 (63 CAS = HMNMX2 pairs, covers
// 2 locations at once) + rank weights (2k-15). Loads stay fp32 (float2),
// converted once to half2. Per-location result combined in fp32; block
// partials + last-block-done final reduction (graph-replay safe).

static constexpr int M_ENS = 16;
static constexpr int NLOC = 6 * 2 * 192 * 288;  // 663552
static constexpr int NQ2 = NLOC / 2;            // 331776 float2 quads
static constexpr int THREADS = 256;
static constexpr int BLOCKS = NQ2 / THREADS;    // 1296 (exact)

__device__ float g_part[BLOCKS];
__device__ unsigned int g_ticket = 0;  // reset by last block each launch

#define CAS2(a, b)                              \
    do {                                        \
        __half2 _lo = __hmin2(p[a], p[b]);      \
        __half2 _hi = __hmax2(p[a], p[b]);      \
        p[a] = _lo;                             \
        p[b] = _hi;                             \
    } while (0)

__device__ __forceinline__ __half2 hc(float c) {
    return __halves2half2(__float2half_rn(c), __float2half_rn(c));
}

__global__ __launch_bounds__(THREADS, 4) void crps_kernel(
    const float2* __restrict__ target2, const float2* __restrict__ pred2,
    float* __restrict__ out) {
    const int q = blockIdx.x * THREADS + threadIdx.x;  // < NQ2 (exact grid)

    __half2 p[M_ENS];
    const float2 tf = target2[q];

    // Two batches of 8 float2 loads -> convert, keeps fp32 live-range bounded
    {
        float2 v[8];
#pragma unroll
        for (int i = 0; i < 8; i++) v[i] = pred2[(long long)i * NQ2 + q];
#pragma unroll
        for (int i = 0; i < 8; i++) p[i] = __floats2half2_rn(v[i].x, v[i].y);
    }
    {
        float2 v[8];
#pragma unroll
        for (int i = 0; i < 8; i++) v[i] = pred2[(long long)(i + 8) * NQ2 + q];
#pragma unroll
        for (int i = 0; i < 8; i++) p[i + 8] = __floats2half2_rn(v[i].x, v[i].y);
    }
    const __half2 t2 = __floats2half2_rn(tf.x, tf.y);

    // skill2 = sum_i |p_i - t|  (per-lane, 2 locations)
    __half2 skill2 = __habs2(__hsub2(p[0], t2));
#pragma unroll
    for (int i = 1; i < M_ENS; i++)
        skill2 = __hadd2(skill2, __habs2(__hsub2(p[i], t2)));

    // Batcher merge-exchange network, 16 inputs, 63 comparators (in half2)
    CAS2(0, 8);  CAS2(1, 9);  CAS2(2, 10); CAS2(3, 11);
    CAS2(4, 12); CAS2(5, 13); CAS2(6, 14); CAS2(7, 15);
    CAS2(0, 4);  CAS2(1, 5);  CAS2(2, 6);  CAS2(3, 7);
    CAS2(8, 12); CAS2(9, 13); CAS2(10, 14); CAS2(11, 15);
    CAS2(4, 8);  CAS2(5, 9);  CAS2(6, 10); CAS2(7, 11);
    CAS2(0, 2);  CAS2(1, 3);  CAS2(4, 6);  CAS2(5, 7);
    CAS2(8, 10); CAS2(9, 11); CAS2(12, 14); CAS2(13, 15);
    CAS2(2, 8);  CAS2(3, 9);  CAS2(6, 12); CAS2(7, 13);
    CAS2(2, 4);  CAS2(3, 5);  CAS2(6, 8);  CAS2(7, 9);
    CAS2(10, 12); CAS2(11, 13);
    CAS2(0, 1);  CAS2(2, 3);  CAS2(4, 5);  CAS2(6, 7);
    CAS2(8, 9);  CAS2(10, 11); CAS2(12, 13); CAS2(14, 15);
    CAS2(1, 8);  CAS2(3, 10); CAS2(5, 12); CAS2(7, 14);
    CAS2(1, 4);  CAS2(3, 6);  CAS2(5, 8);  CAS2(7, 10);
    CAS2(9, 12); CAS2(11, 14);
    CAS2(1, 2);  CAS2(3, 4);  CAS2(5, 6);  CAS2(7, 8);
    CAS2(9, 10); CAS2(11, 12); CAS2(13, 14);

    // sum_{i<j}|p_i - p_j| = sum_k (2k-15) * p_sorted[k]
    __half2 ws2 = __hmul2(hc(-15.0f), p[0]);
#pragma unroll
    for (int k = 1; k < M_ENS; k++)
        ws2 = __hfma2(hc((float)(2 * k - 15)), p[k], ws2);

    // combine per-location in fp32
    const float2 sk = __half22float2(skill2);
    const float2 wsf = __half22float2(ws2);
    float crps = (sk.x + sk.y) * (1.0f / 16.0f) - (wsf.x + wsf.y) * (1.0f / 240.0f);

    // ---- block reduction ----
    __shared__ float warp_sums[THREADS / 32];
    float v = crps;
#pragma unroll
    for (int o = 16; o > 0; o >>= 1) v += __shfl_xor_sync(0xFFFFFFFFu, v, o);
    const int lane = threadIdx.x & 31;
    const int wid = threadIdx.x >> 5;
    if (lane == 0) warp_sums[wid] = v;
    __syncthreads();

    __shared__ bool s_last;
    if (wid == 0) {
        float bv = (lane < (THREADS / 32)) ? warp_sums[lane] : 0.0f;
#pragma unroll
        for (int o = 4; o > 0; o >>= 1) bv += __shfl_xor_sync(0xFFFFFFFFu, bv, o);
        if (lane == 0) {
            g_part[blockIdx.x] = bv;
            __threadfence();
            unsigned int tk = atomicAdd(&g_ticket, 1u);
            s_last = (tk == (unsigned int)(BLOCKS - 1));
        }
    }
    __syncthreads();

    // ---- last block: sum partials, write scalar, reset ticket ----
    if (s_last) {
        double acc = 0.0;
        for (int i = threadIdx.x; i < BLOCKS; i += THREADS) acc += (double)g_part[i];
#pragma unroll
        for (int o = 16; o > 0; o >>= 1) acc += __shfl_xor_sync(0xFFFFFFFFu, acc, o);
        __shared__ double warp_d[THREADS / 32];
        if (lane == 0) warp_d[wid] = acc;
        __syncthreads();
        if (wid == 0) {
            double bd = (lane < (THREADS / 32)) ? warp_d[lane] : 0.0;
#pragma unroll
            for (int o = 4; o > 0; o >>= 1) bd += __shfl_xor_sync(0xFFFFFFFFu, bd, o);
            if (lane == 0) {
                out[0] = (float)(bd / (double)NLOC);
                __threadfence();
                g_ticket = 0;  // deterministic across graph replays
            }
        }
    }
}

extern "C" void kernel_launch(void* const* d_in, const int* in_sizes, int n_in,
                              void* d_out, int out_size) {
    const float* a = (const float*)d_in[0];
    const float* b = (const float*)d_in[1];
    const float* target = a;
    const float* pred = b;
    if (n_in >= 2 && in_sizes[0] > in_sizes[1]) {
        target = b;
        pred = a;
    }
    crps_kernel<<<BLOCKS, THREADS>>>((const float2*)target, (const float2*)pred,
                                     (float*)d_out);
}